// round 1
// baseline (speedup 1.0000x reference)
#include <cuda_runtime.h>
#include <cuda_bf16.h>

// Inputs (metadata order):
//   d_in[0] input_values   float32 [1024]
//   d_in[1] weight_matrix  float32 [16384*16384]  (row-major [N,N])
//   d_in[2] biases         float32 [16384]
//   d_in[3] act_ids        int32   [16384]   0=identity 1=relu 2=softsign
//   d_in[4] input_indices  int32   [1024]
//   d_in[5] output_indices int32   [256]
// Output: float32 [256]
//
// total[j] = sum_i input_values[i] * W[input_indices[i], j] + biases[j]
// out[o]   = act(total[output_indices[o]])
// Only the 256 needed columns are computed (sparse-aware GEMV).

__global__ void __launch_bounds__(1024, 2)
custom_network_kernel(const float* __restrict__ in_vals,
                      const float* __restrict__ W,
                      const float* __restrict__ bias,
                      const int*   __restrict__ act_ids,
                      const int*   __restrict__ in_idx,
                      const int*   __restrict__ out_idx,
                      float*       __restrict__ out,
                      int n_in, long long N)
{
    const int j = out_idx[blockIdx.x];      // output column (uniform per CTA)
    const int t = threadIdx.x;

    // Each thread handles one (or a strided few) input rows: single scattered
    // LDG per thread, issued immediately -> maximum MLP across the chip.
    float partial = 0.0f;
    for (int i = t; i < n_in; i += blockDim.x) {
        const long long row = (long long)in_idx[i];
        partial += in_vals[i] * __ldg(&W[row * N + (long long)j]);
    }

    // Block reduction: warp shuffle, then cross-warp via shared memory.
    __shared__ float sm[32];
    #pragma unroll
    for (int off = 16; off > 0; off >>= 1)
        partial += __shfl_xor_sync(0xFFFFFFFFu, partial, off);

    const int lane = t & 31;
    const int wid  = t >> 5;
    if (lane == 0) sm[wid] = partial;
    __syncthreads();

    if (wid == 0) {
        const int nwarps = (blockDim.x + 31) >> 5;
        float v = (lane < nwarps) ? sm[lane] : 0.0f;
        #pragma unroll
        for (int off = 16; off > 0; off >>= 1)
            v += __shfl_xor_sync(0xFFFFFFFFu, v, off);

        if (lane == 0) {
            const float total = v + bias[j];
            const int   a     = act_ids[j];
            const float relu  = fmaxf(total, 0.0f);
            const float ssign = total / (1.0f + fabsf(total));
            out[blockIdx.x] = (a == 1) ? relu : ((a == 2) ? ssign : total);
        }
    }
}

extern "C" void kernel_launch(void* const* d_in, const int* in_sizes, int n_in_args,
                              void* d_out, int out_size)
{
    const float* in_vals = (const float*)d_in[0];
    const float* W       = (const float*)d_in[1];
    const float* bias    = (const float*)d_in[2];
    const int*   act_ids = (const int*)  d_in[3];
    const int*   in_idx  = (const int*)  d_in[4];
    const int*   out_idx = (const int*)  d_in[5];
    float*       out     = (float*)      d_out;

    const int n_in = in_sizes[0];          // 1024
    const long long N = (long long)in_sizes[2]; // 16384 (bias length)

    custom_network_kernel<<<out_size, 1024>>>(
        in_vals, W, bias, act_ids, in_idx, out_idx, out, n_in, N);
}